// round 8
// baseline (speedup 1.0000x reference)
#include <cuda_runtime.h>
#include <cstdint>
#include <cmath>

// ---------------------------------------------------------------- constants
#define BB   2
#define TT   2048
#define CC   1024
#define NH   16
#define HD   64
#define BT   (BB*TT)          // 4096
#define C3   (3*CC)           // 3072
#define SCALE 0.125f

// ---------------------------------------------------------------- scratch
__device__ float g_qkv[(size_t)BT * C3];        // Q,K regions (cols<2048), col-permuted
__device__ float g_vt [(size_t)BB*NH*HD*TT];    // V transposed [b,h,d,token], tok-permuted
__device__ float g_y  [(size_t)BT * CC];        // attention out, col-permuted, tf32
__device__ float g_xp [(size_t)BT * CC];        // x rounded+col-permuted
__device__ float g_waT[(size_t)C3 * CC];        // w_attn^T [N,K], K-permuted, tf32
__device__ float g_wpT[(size_t)CC * CC];        // w_proj^T [N,K], K-permuted, tf32

// ---------------------------------------------------------------- utils
__device__ __forceinline__ uint32_t smem_u32(const void* p) {
    uint32_t a;
    asm("{ .reg .u64 t; cvta.to.shared.u64 t, %1; cvt.u32.u64 %0, t; }" : "=r"(a) : "l"(p));
    return a;
}
__device__ __forceinline__ float rn_tf32(float x) {
    uint32_t r;
    asm("cvt.rna.tf32.f32 %0, %1;" : "=r"(r) : "f"(x));
    return __uint_as_float(r);
}
#define CP_ASYNC16(dst, src) \
    asm volatile("cp.async.cg.shared.global [%0], [%1], 16;\n" :: "r"(dst), "l"(src))
#define CP_COMMIT() asm volatile("cp.async.commit_group;" ::: "memory")
#define CP_WAIT(n)  asm volatile("cp.async.wait_group %0;" :: "n"(n) : "memory")

__device__ __forceinline__ void mma_tf32(float* c, const uint32_t* a, const uint32_t* b) {
    asm volatile(
        "mma.sync.aligned.m16n8k8.row.col.f32.tf32.tf32.f32 "
        "{%0,%1,%2,%3}, {%4,%5,%6,%7}, {%8,%9}, {%0,%1,%2,%3};"
        : "+f"(c[0]), "+f"(c[1]), "+f"(c[2]), "+f"(c[3])
        : "r"(a[0]), "r"(a[1]), "r"(a[2]), "r"(a[3]), "r"(b[0]), "r"(b[1]));
}

// position of natural index u within its 8-group: [0,4,1,5,2,6,3,7]
__device__ __forceinline__ int perm8(int u) { return u < 4 ? 2 * u : 2 * u - 7; }

// ---------------------------------------------------------------- prep
// round to tf32 + permute cols within 8-groups: out[8q+p] = rn(in[8q+gather[p]]),
// gather = [0,4,1,5,2,6,3,7]
__global__ void round_perm_kernel(const float* __restrict__ in, float* __restrict__ out) {
    size_t i = ((size_t)blockIdx.x * blockDim.x + threadIdx.x) * 8;
    float4 a = *(const float4*)(in + i);
    float4 b = *(const float4*)(in + i + 4);
    float4 o0 = make_float4(rn_tf32(a.x), rn_tf32(b.x), rn_tf32(a.y), rn_tf32(b.y));
    float4 o1 = make_float4(rn_tf32(a.z), rn_tf32(b.z), rn_tf32(a.w), rn_tf32(b.w));
    *(float4*)(out + i)     = o0;
    *(float4*)(out + i + 4) = o1;
}

// in [K,N] -> out [N,K] with out[n][p] = rn(in[(p&~7)|gather[p&7]][n])
__global__ void transpose_perm_kernel(const float* __restrict__ in, float* __restrict__ out,
                                      int K, int N) {
    __shared__ float tsm[32][33];
    int k0 = blockIdx.y * 32, n0 = blockIdx.x * 32;
    int tx = threadIdx.x, ty = threadIdx.y;     // 32 x 8
#pragma unroll
    for (int i = 0; i < 32; i += 8)
        tsm[ty + i][tx] = in[(size_t)(k0 + ty + i) * N + n0 + tx];
    __syncthreads();
    int kk = (tx & ~7) | (((tx & 7) >> 1) + (tx & 1) * 4);   // gather
#pragma unroll
    for (int i = 0; i < 32; i += 8)
        out[(size_t)(n0 + ty + i) * K + k0 + tx] = rn_tf32(tsm[kk][ty + i]);
}

// ---------------------------------------------------------------- tf32 GEMM
// C[M,N] = A[M,Kp] @ Bt[N,Kp]^T + bias[N]. Both operands K-permuted in 8-groups.
// 128x128 tile, BK=32, 3-stage, XOR-swizzled smem (32-float rows), all frag
// loads LDS.64. mode: 0=plain store, 1=QKV (Q/K col-perm -> C, V -> vt).
#define GBM 128
#define GBN 128
#define GBK 32
#define GSTG 3
#define TILE32 (128 * 32)
#define GEMM_SMEM (GSTG * 2 * TILE32 * 4)    // 98304 B

__device__ __forceinline__ void gemm_load_stage(
    float* As, float* Bs, const float* A, const float* Bt,
    int m0, int n0, int K, int kb, int tid)
{
    int s = kb % GSTG;
    uint32_t abase = smem_u32(As + s * TILE32);
    uint32_t bbase = smem_u32(Bs + s * TILE32);
    const float* ag = A  + (size_t)m0 * K + (size_t)kb * GBK;
    const float* bg = Bt + (size_t)n0 * K + (size_t)kb * GBK;
#pragma unroll
    for (int i = 0; i < 4; i++) {
        int idx = tid + i * 256;
        int row = idx >> 3, c4 = idx & 7;
        int off = (row * 32 + ((c4 * 4) ^ (8 * (row & 3)))) * 4;
        CP_ASYNC16(abase + off, ag + (size_t)row * K + c4 * 4);
    }
#pragma unroll
    for (int i = 0; i < 4; i++) {
        int idx = tid + i * 256;
        int row = idx >> 3, c4 = idx & 7;
        int off = (row * 32 + ((c4 * 4) ^ (8 * (row & 3)))) * 4;
        CP_ASYNC16(bbase + off, bg + (size_t)row * K + c4 * 4);
    }
}

__global__ __launch_bounds__(256, 2) void gemm_tf32(
    const float* __restrict__ A, const float* __restrict__ Bt,
    const float* __restrict__ bias, float* __restrict__ C,
    float* __restrict__ vt, int M, int N, int K, int mode)
{
    extern __shared__ float smf[];
    float* As = smf;
    float* Bs = smf + GSTG * TILE32;

    const int tid = threadIdx.x, wid = tid >> 5, lane = tid & 31;
    const int g = lane >> 2, t = lane & 3;
    const int wm = wid & 3, wn = wid >> 2;
    const int m0 = blockIdx.y * GBM, n0 = blockIdx.x * GBN;
    const int NCH = K / GBK;
    const int sw = 8 * (g & 3);

    float acc[2][8][4];
#pragma unroll
    for (int mt = 0; mt < 2; mt++)
#pragma unroll
        for (int nt = 0; nt < 8; nt++)
#pragma unroll
            for (int k = 0; k < 4; k++) acc[mt][nt][k] = 0.f;

#pragma unroll
    for (int s = 0; s < GSTG - 1; s++) {
        gemm_load_stage(As, Bs, A, Bt, m0, n0, K, s, tid);
        CP_COMMIT();
    }

    for (int kb = 0; kb < NCH; kb++) {
        CP_WAIT(GSTG - 2);
        __syncthreads();

        if (kb + GSTG - 1 < NCH)
            gemm_load_stage(As, Bs, A, Bt, m0, n0, K, kb + GSTG - 1, tid);
        CP_COMMIT();

        const float* as = As + (kb % GSTG) * TILE32;
        const float* bs = Bs + (kb % GSTG) * TILE32;
#pragma unroll
        for (int ks = 0; ks < 4; ks++) {
            const int cc = (ks * 8 + 2 * t) ^ sw;     // perm pair (k=t, k=t+4)
            uint32_t af[2][4], bf[8][2];
#pragma unroll
            for (int mt = 0; mt < 2; mt++) {
                int r = wm * 32 + mt * 16 + g;
                float2 a0 = *(const float2*)(as + r * 32 + cc);
                float2 a1 = *(const float2*)(as + (r + 8) * 32 + cc);
                af[mt][0] = __float_as_uint(a0.x);
                af[mt][1] = __float_as_uint(a1.x);
                af[mt][2] = __float_as_uint(a0.y);
                af[mt][3] = __float_as_uint(a1.y);
            }
#pragma unroll
            for (int nt = 0; nt < 8; nt++) {
                int n = wn * 64 + nt * 8 + g;
                float2 bv = *(const float2*)(bs + n * 32 + cc);
                bf[nt][0] = __float_as_uint(bv.x);
                bf[nt][1] = __float_as_uint(bv.y);
            }
#pragma unroll
            for (int mt = 0; mt < 2; mt++)
#pragma unroll
                for (int nt = 0; nt < 8; nt++)
                    mma_tf32(acc[mt][nt], af[mt], bf[nt]);
        }
    }

    // epilogue
#pragma unroll
    for (int mt = 0; mt < 2; mt++) {
        int r0 = m0 + wm * 32 + mt * 16 + g;
#pragma unroll
        for (int nt = 0; nt < 8; nt++) {
            int c = n0 + wn * 64 + nt * 8 + 2 * t;     // even natural col
            float2 b2 = *(const float2*)(bias + c);
            float2 v0 = make_float2(acc[mt][nt][0] + b2.x, acc[mt][nt][1] + b2.y);
            float2 v1 = make_float2(acc[mt][nt][2] + b2.x, acc[mt][nt][3] + b2.y);
            if (mode == 1) {
                v0.x = rn_tf32(v0.x); v0.y = rn_tf32(v0.y);
                v1.x = rn_tf32(v1.x); v1.y = rn_tf32(v1.y);
                if (c < 2048) {
                    // Q/K: col-permute within 8-groups
                    int c0p = (c & ~7) | perm8(c & 7);
                    int c1p = (c & ~7) | perm8((c & 7) + 1);
                    C[(size_t)r0 * N + c0p] = v0.x;
                    C[(size_t)r0 * N + c1p] = v0.y;
                    C[(size_t)(r0 + 8) * N + c0p] = v1.x;
                    C[(size_t)(r0 + 8) * N + c1p] = v1.y;
                } else {
                    // V: transpose into vt[b,h,d,token], token-permuted
                    int h  = (c - 2048) >> 6;
                    int d0 = (c - 2048) & 63;          // even
                    int b0  = r0 >> 11;
                    int tp0 = ((r0 & 2047) & ~7) | perm8(r0 & 7);
                    int tp1 = (((r0 + 8) & 2047) & ~7) | perm8((r0 + 8) & 7);
                    float* vb = vt + ((size_t)(b0 * NH + h) * HD + d0) * TT;
                    vb[tp0]      = v0.x;
                    vb[TT + tp0] = v0.y;
                    vb[tp1]      = v1.x;
                    vb[TT + tp1] = v1.y;
                }
            } else {
                *(float2*)(C + (size_t)r0 * N + c) = v0;
                *(float2*)(C + (size_t)(r0 + 8) * N + c) = v1;
            }
        }
    }
}

// ---------------------------------------------------------------- attention
// Q,K col-permuted (from QKV epilogue); V staged from vt (transposed,
// token-permuted). All fragment loads LDS.64. Stride 72 (== 8 mod 32 banks).
#define AQ 64
#define AK 64
#define ASTR 72
#define SM_QS 0
#define SM_KS (64*ASTR)                      // 4608
#define SM_VS (SM_KS + 2*64*ASTR)            // 13824
#define SM_PS (SM_VS + 2*64*ASTR)            // 23040
#define ATTN_SMEM ((SM_PS + 64*ASTR) * 4)    // 110592 B

__device__ __forceinline__ void attn_load_kv(float* sm, const float* __restrict__ qkv,
                                             const float* __restrict__ vt,
                                             int b, int h, int kt, int buf, int tid)
{
    // K: 64 token-rows x 64 d-cols from qkv (already col-permuted)
    const float* kbase = qkv + ((size_t)(b * TT + kt * AK)) * C3 + CC + h * HD;
    uint32_t kdst = smem_u32(sm + SM_KS + buf * 64 * ASTR);
#pragma unroll
    for (int i = 0; i < 8; i++) {                       // FIX: full 64 rows
        int idx = tid + i * 128;
        int row = idx >> 4, c4 = idx & 15;
        CP_ASYNC16(kdst + (row * ASTR + c4 * 4) * 4, kbase + (size_t)row * C3 + c4 * 4);
    }
    // V: 64 d-rows x 64 token-cols from vt (token-permuted)
    const float* vbase = vt + ((size_t)(b * NH + h) * HD) * TT + kt * AK;
    uint32_t vdst = smem_u32(sm + SM_VS + buf * 64 * ASTR);
#pragma unroll
    for (int i = 0; i < 8; i++) {                       // FIX: full 64x64 tile
        int idx = tid + i * 128;
        int d = idx >> 4, c4 = idx & 15;
        CP_ASYNC16(vdst + (d * ASTR + c4 * 4) * 4, vbase + (size_t)d * TT + c4 * 4);
    }
}

__global__ __launch_bounds__(128, 2) void attn_tc(const float* __restrict__ qkv,
                                                  const float* __restrict__ vt,
                                                  float* __restrict__ y)
{
    extern __shared__ float sm[];
    const int tid = threadIdx.x;
    const int wid = tid >> 5, lane = tid & 31;
    const int g = lane >> 2, t = lane & 3;
    const int qt = gridDim.x - 1 - blockIdx.x;
    const int h  = blockIdx.y;
    const int b  = blockIdx.z;
    const int q0 = qt * AQ;
    const int r0 = wid * 16 + g;

    {
        const float* qbase = qkv + ((size_t)(b * TT + q0)) * C3 + h * HD;
#pragma unroll
        for (int i = 0; i < 8; i++) {
            int idx = tid + i * 128;
            int row = idx >> 4, c4 = idx & 15;
            float4 v = *(const float4*)(qbase + (size_t)row * C3 + c4 * 4);
            v.x *= SCALE; v.y *= SCALE; v.z *= SCALE; v.w *= SCALE;
            *(float4*)(&sm[SM_QS + row * ASTR + c4 * 4]) = v;
        }
    }
    attn_load_kv(sm, qkv, vt, b, h, 0, 0, tid);
    CP_COMMIT();
    __syncthreads();

    uint32_t qf[8][4];
#pragma unroll
    for (int ds = 0; ds < 8; ds++) {
        float2 q0v = *(const float2*)(&sm[SM_QS + r0 * ASTR + ds * 8 + 2 * t]);
        float2 q1v = *(const float2*)(&sm[SM_QS + (r0 + 8) * ASTR + ds * 8 + 2 * t]);
        qf[ds][0] = __float_as_uint(q0v.x);
        qf[ds][1] = __float_as_uint(q1v.x);
        qf[ds][2] = __float_as_uint(q0v.y);
        qf[ds][3] = __float_as_uint(q1v.y);
    }

    float oacc[8][4];
#pragma unroll
    for (int nt = 0; nt < 8; nt++)
#pragma unroll
        for (int k = 0; k < 4; k++) oacc[nt][k] = 0.f;
    float mrow0 = -INFINITY, mrow1 = -INFINITY, lrow0 = 0.f, lrow1 = 0.f;

    const int pp0 = perm8(2 * t), pp1 = perm8(2 * t + 1);

    for (int kt = 0; kt <= qt; kt++) {
        const int buf = kt & 1;
        CP_WAIT(0);
        __syncthreads();
        if (kt < qt) { attn_load_kv(sm, qkv, vt, b, h, kt + 1, buf ^ 1, tid); CP_COMMIT(); }

        const float* ks = sm + SM_KS + buf * 64 * ASTR;
        const float* vs = sm + SM_VS + buf * 64 * ASTR;

        // S = Q K^T
        float sacc[8][4];
#pragma unroll
        for (int nt = 0; nt < 8; nt++)
#pragma unroll
            for (int k = 0; k < 4; k++) sacc[nt][k] = 0.f;
#pragma unroll
        for (int ds = 0; ds < 8; ds++) {
            uint32_t bf[8][2];
#pragma unroll
            for (int nt = 0; nt < 8; nt++) {
                float2 kv = *(const float2*)(&ks[(nt * 8 + g) * ASTR + ds * 8 + 2 * t]);
                bf[nt][0] = __float_as_uint(kv.x);
                bf[nt][1] = __float_as_uint(kv.y);
            }
#pragma unroll
            for (int nt = 0; nt < 8; nt++)
                mma_tf32(sacc[nt], qf[ds], bf[nt]);
        }

        if (kt == qt) {
#pragma unroll
            for (int nt = 0; nt < 8; nt++) {
                int c = nt * 8 + 2 * t;
                if (c     > r0)     sacc[nt][0] = -1e30f;
                if (c + 1 > r0)     sacc[nt][1] = -1e30f;
                if (c     > r0 + 8) sacc[nt][2] = -1e30f;
                if (c + 1 > r0 + 8) sacc[nt][3] = -1e30f;
            }
        }

        // online softmax
        float tm0 = -INFINITY, tm1 = -INFINITY;
#pragma unroll
        for (int nt = 0; nt < 8; nt++) {
            tm0 = fmaxf(tm0, fmaxf(sacc[nt][0], sacc[nt][1]));
            tm1 = fmaxf(tm1, fmaxf(sacc[nt][2], sacc[nt][3]));
        }
        tm0 = fmaxf(tm0, __shfl_xor_sync(0xffffffffu, tm0, 1));
        tm0 = fmaxf(tm0, __shfl_xor_sync(0xffffffffu, tm0, 2));
        tm1 = fmaxf(tm1, __shfl_xor_sync(0xffffffffu, tm1, 1));
        tm1 = fmaxf(tm1, __shfl_xor_sync(0xffffffffu, tm1, 2));
        float m0 = fmaxf(mrow0, tm0), m1 = fmaxf(mrow1, tm1);
        float a0 = __expf(mrow0 - m0), a1 = __expf(mrow1 - m1);
        mrow0 = m0; mrow1 = m1;
        float rs0 = 0.f, rs1 = 0.f;
#pragma unroll
        for (int nt = 0; nt < 8; nt++) {
            sacc[nt][0] = __expf(sacc[nt][0] - m0); rs0 += sacc[nt][0];
            sacc[nt][1] = __expf(sacc[nt][1] - m0); rs0 += sacc[nt][1];
            sacc[nt][2] = __expf(sacc[nt][2] - m1); rs1 += sacc[nt][2];
            sacc[nt][3] = __expf(sacc[nt][3] - m1); rs1 += sacc[nt][3];
        }
        rs0 += __shfl_xor_sync(0xffffffffu, rs0, 1);
        rs0 += __shfl_xor_sync(0xffffffffu, rs0, 2);
        rs1 += __shfl_xor_sync(0xffffffffu, rs1, 1);
        rs1 += __shfl_xor_sync(0xffffffffu, rs1, 2);
        lrow0 = lrow0 * a0 + rs0;
        lrow1 = lrow1 * a1 + rs1;
#pragma unroll
        for (int nt = 0; nt < 8; nt++) {
            oacc[nt][0] *= a0; oacc[nt][1] *= a0;
            oacc[nt][2] *= a1; oacc[nt][3] *= a1;
        }

        // stage P token-permuted (matches vt's token order)
#pragma unroll
        for (int nt = 0; nt < 8; nt++) {
            int cb = SM_PS + nt * 8;
            sm[cb + r0 * ASTR + pp0]       = rn_tf32(sacc[nt][0]);
            sm[cb + r0 * ASTR + pp1]       = rn_tf32(sacc[nt][1]);
            sm[cb + (r0 + 8) * ASTR + pp0] = rn_tf32(sacc[nt][2]);
            sm[cb + (r0 + 8) * ASTR + pp1] = rn_tf32(sacc[nt][3]);
        }
        __syncwarp();

        // O += P @ V   (P rows x V^T[d][token]; all LDS.64)
#pragma unroll
        for (int kk = 0; kk < 8; kk++) {
            uint32_t af[4];
            float2 p0 = *(const float2*)(&sm[SM_PS + r0 * ASTR + kk * 8 + 2 * t]);
            float2 p1 = *(const float2*)(&sm[SM_PS + (r0 + 8) * ASTR + kk * 8 + 2 * t]);
            af[0] = __float_as_uint(p0.x);
            af[1] = __float_as_uint(p1.x);
            af[2] = __float_as_uint(p0.y);
            af[3] = __float_as_uint(p1.y);
            uint32_t bf[8][2];
#pragma unroll
            for (int nt = 0; nt < 8; nt++) {
                float2 vv = *(const float2*)(&vs[(nt * 8 + g) * ASTR + kk * 8 + 2 * t]);
                bf[nt][0] = __float_as_uint(vv.x);
                bf[nt][1] = __float_as_uint(vv.y);
            }
#pragma unroll
            for (int nt = 0; nt < 8; nt++)
                mma_tf32(oacc[nt], af, bf[nt]);
        }
    }

    // normalize + store, col-permuted (feeds proj GEMM's permuted A)
    float inv0 = 1.0f / lrow0, inv1 = 1.0f / lrow1;
    float* ybase = y + ((size_t)(b * TT + q0)) * CC + h * HD;
#pragma unroll
    for (int nt = 0; nt < 8; nt++) {
        int cb = nt * 8;
        ybase[(size_t)r0 * CC + cb + pp0]       = rn_tf32(oacc[nt][0] * inv0);
        ybase[(size_t)r0 * CC + cb + pp1]       = rn_tf32(oacc[nt][1] * inv0);
        ybase[(size_t)(r0 + 8) * CC + cb + pp0] = rn_tf32(oacc[nt][2] * inv1);
        ybase[(size_t)(r0 + 8) * CC + cb + pp1] = rn_tf32(oacc[nt][3] * inv1);
    }
}

// ---------------------------------------------------------------- launch
extern "C" void kernel_launch(void* const* d_in, const int* in_sizes, int n_in,
                              void* d_out, int out_size)
{
    const float* x      = (const float*)d_in[0];
    const float* w_attn = (const float*)d_in[1];
    const float* b_attn = (const float*)d_in[2];
    const float* w_proj = (const float*)d_in[3];
    const float* b_proj = (const float*)d_in[4];
    float* out = (float*)d_out;

    float *qkv, *vt, *yb, *xp, *waT, *wpT;
    cudaGetSymbolAddress((void**)&qkv, g_qkv);
    cudaGetSymbolAddress((void**)&vt,  g_vt);
    cudaGetSymbolAddress((void**)&yb,  g_y);
    cudaGetSymbolAddress((void**)&xp,  g_xp);
    cudaGetSymbolAddress((void**)&waT, g_waT);
    cudaGetSymbolAddress((void**)&wpT, g_wpT);

    cudaFuncSetAttribute(gemm_tf32, cudaFuncAttributeMaxDynamicSharedMemorySize, GEMM_SMEM);
    cudaFuncSetAttribute(attn_tc,   cudaFuncAttributeMaxDynamicSharedMemorySize, ATTN_SMEM);

    // 0) prep: round+permute x; transpose+permute weights
    round_perm_kernel<<<(BT * CC) / (256 * 8), 256>>>(x, xp);
    transpose_perm_kernel<<<dim3(C3 / 32, CC / 32), dim3(32, 8)>>>(w_attn, waT, CC, C3);
    transpose_perm_kernel<<<dim3(CC / 32, CC / 32), dim3(32, 8)>>>(w_proj, wpT, CC, CC);

    // 1) QKV GEMM (Q/K -> qkv permuted, V -> vt transposed)
    gemm_tf32<<<dim3(C3 / GBN, BT / GBM), 256, GEMM_SMEM>>>(xp, waT, b_attn, qkv, vt,
                                                            BT, C3, CC, 1);

    // 2) causal attention
    attn_tc<<<dim3(TT / AQ, NH, BB), 128, ATTN_SMEM>>>(qkv, vt, yb);

    // 3) out = y @ w_proj + b_proj
    gemm_tf32<<<dim3(CC / GBN, BT / GBM), 256, GEMM_SMEM>>>(yb, wpT, b_proj, out, vt,
                                                            BT, CC, CC, 0);
}

// round 9
// speedup vs baseline: 1.0730x; 1.0730x over previous
#include <cuda_runtime.h>
#include <cstdint>
#include <cmath>

// ---------------------------------------------------------------- constants
#define BB   2
#define TT   2048
#define CC   1024
#define NH   16
#define HD   64
#define BT   (BB*TT)          // 4096
#define C3   (3*CC)           // 3072
#define SCALE 0.125f

// ---------------------------------------------------------------- scratch
__device__ float g_qkv[(size_t)BT * C3];        // Q,K regions (cols<2048), col-permuted
__device__ float g_vt [(size_t)BB*NH*HD*TT];    // V transposed [b,h,d,token], tok-permuted
__device__ float g_y  [(size_t)BT * CC];        // attention out, col-permuted, tf32
__device__ float g_xp [(size_t)BT * CC];        // x rounded+col-permuted
__device__ float g_waT[(size_t)C3 * CC];        // w_attn^T [N,K], K-permuted, tf32
__device__ float g_wpT[(size_t)CC * CC];        // w_proj^T [N,K], K-permuted, tf32

// ---------------------------------------------------------------- utils
__device__ __forceinline__ uint32_t smem_u32(const void* p) {
    uint32_t a;
    asm("{ .reg .u64 t; cvta.to.shared.u64 t, %1; cvt.u32.u64 %0, t; }" : "=r"(a) : "l"(p));
    return a;
}
__device__ __forceinline__ float rn_tf32(float x) {
    uint32_t r;
    asm("cvt.rna.tf32.f32 %0, %1;" : "=r"(r) : "f"(x));
    return __uint_as_float(r);
}
#define CP_ASYNC16(dst, src) \
    asm volatile("cp.async.cg.shared.global [%0], [%1], 16;\n" :: "r"(dst), "l"(src))
#define CP_COMMIT() asm volatile("cp.async.commit_group;" ::: "memory")
#define CP_WAIT(n)  asm volatile("cp.async.wait_group %0;" :: "n"(n) : "memory")

__device__ __forceinline__ void mma_tf32(float* c, const uint32_t* a, const uint32_t* b) {
    asm volatile(
        "mma.sync.aligned.m16n8k8.row.col.f32.tf32.tf32.f32 "
        "{%0,%1,%2,%3}, {%4,%5,%6,%7}, {%8,%9}, {%0,%1,%2,%3};"
        : "+f"(c[0]), "+f"(c[1]), "+f"(c[2]), "+f"(c[3])
        : "r"(a[0]), "r"(a[1]), "r"(a[2]), "r"(a[3]), "r"(b[0]), "r"(b[1]));
}

// ldmatrix x4: four 8x8 b16 tiles == four 8x4 tf32 tiles, 1 instruction
__device__ __forceinline__ void ldsm_x4(uint32_t* r, uint32_t addr) {
    asm volatile("ldmatrix.sync.aligned.m8n8.x4.shared.b16 {%0,%1,%2,%3}, [%4];"
        : "=r"(r[0]), "=r"(r[1]), "=r"(r[2]), "=r"(r[3]) : "r"(addr));
}

// position of natural index u within its 8-group: [0,4,1,5,2,6,3,7]
__device__ __forceinline__ int perm8(int u) { return u < 4 ? 2 * u : 2 * u - 7; }

// ---------------------------------------------------------------- prep
__global__ void round_perm_kernel(const float* __restrict__ in, float* __restrict__ out) {
    size_t i = ((size_t)blockIdx.x * blockDim.x + threadIdx.x) * 8;
    float4 a = *(const float4*)(in + i);
    float4 b = *(const float4*)(in + i + 4);
    float4 o0 = make_float4(rn_tf32(a.x), rn_tf32(b.x), rn_tf32(a.y), rn_tf32(b.y));
    float4 o1 = make_float4(rn_tf32(a.z), rn_tf32(b.z), rn_tf32(a.w), rn_tf32(b.w));
    *(float4*)(out + i)     = o0;
    *(float4*)(out + i + 4) = o1;
}

__global__ void transpose_perm_kernel(const float* __restrict__ in, float* __restrict__ out,
                                      int K, int N) {
    __shared__ float tsm[32][33];
    int k0 = blockIdx.y * 32, n0 = blockIdx.x * 32;
    int tx = threadIdx.x, ty = threadIdx.y;     // 32 x 8
#pragma unroll
    for (int i = 0; i < 32; i += 8)
        tsm[ty + i][tx] = in[(size_t)(k0 + ty + i) * N + n0 + tx];
    __syncthreads();
    int kk = (tx & ~7) | (((tx & 7) >> 1) + (tx & 1) * 4);   // gather
#pragma unroll
    for (int i = 0; i < 32; i += 8)
        out[(size_t)(n0 + ty + i) * K + k0 + tx] = rn_tf32(tsm[kk][ty + i]);
}

// ---------------------------------------------------------------- tf32 GEMM
// C[M,N] = A[M,Kp] @ Bt[N,Kp]^T + bias[N]. 128x128 tile, BK=32, 3-stage,
// XOR swizzle 4*(row&7) (ldmatrix-phase conflict-free), ldmatrix fragments.
#define GBM 128
#define GBN 128
#define GBK 32
#define GSTG 3
#define TILE32 (128 * 32)
#define GEMM_SMEM (GSTG * 2 * TILE32 * 4)    // 98304 B

__device__ __forceinline__ void gemm_load_stage(
    float* As, float* Bs, const float* A, const float* Bt,
    int m0, int n0, int K, int kb, int tid)
{
    int s = kb % GSTG;
    uint32_t abase = smem_u32(As + s * TILE32);
    uint32_t bbase = smem_u32(Bs + s * TILE32);
    const float* ag = A  + (size_t)m0 * K + (size_t)kb * GBK;
    const float* bg = Bt + (size_t)n0 * K + (size_t)kb * GBK;
#pragma unroll
    for (int i = 0; i < 4; i++) {
        int idx = tid + i * 256;
        int row = idx >> 3, c4 = idx & 7;
        int off = (row * 32 + ((c4 * 4) ^ (4 * (row & 7)))) * 4;
        CP_ASYNC16(abase + off, ag + (size_t)row * K + c4 * 4);
    }
#pragma unroll
    for (int i = 0; i < 4; i++) {
        int idx = tid + i * 256;
        int row = idx >> 3, c4 = idx & 7;
        int off = (row * 32 + ((c4 * 4) ^ (4 * (row & 7)))) * 4;
        CP_ASYNC16(bbase + off, bg + (size_t)row * K + c4 * 4);
    }
}

__global__ __launch_bounds__(256, 2) void gemm_tf32(
    const float* __restrict__ A, const float* __restrict__ Bt,
    const float* __restrict__ bias, float* __restrict__ C,
    float* __restrict__ vt, int M, int N, int K, int mode)
{
    extern __shared__ float smf[];
    float* As = smf;
    float* Bs = smf + GSTG * TILE32;

    const int tid = threadIdx.x, wid = tid >> 5, lane = tid & 31;
    const int g = lane >> 2, t = lane & 3;
    const int wm = wid & 3, wn = wid >> 2;
    const int m0 = blockIdx.y * GBM, n0 = blockIdx.x * GBN;
    const int NCH = K / GBK;

    // ldmatrix per-lane geometry: quadrant lq (tile select), li (row in tile)
    const int lq = lane >> 3, li = lane & 7;
    const uint32_t sw4 = 4u * (uint32_t)li;          // XOR swizzle for this lane's rows
    const uint32_t ko  = (uint32_t)((lq >> 1) * 4);  // k quadrant offset (0 or 4)
    uint32_t a_rb[2], b_rb[4];                       // row base byte offsets
#pragma unroll
    for (int mt = 0; mt < 2; mt++)
        a_rb[mt] = (uint32_t)(wm * 32 + mt * 16 + (lq & 1) * 8 + li) * 128u;
#pragma unroll
    for (int p = 0; p < 4; p++)
        b_rb[p] = (uint32_t)(wn * 64 + p * 16 + (lq & 1) * 8 + li) * 128u;

    float acc[2][8][4];
#pragma unroll
    for (int mt = 0; mt < 2; mt++)
#pragma unroll
        for (int nt = 0; nt < 8; nt++)
#pragma unroll
            for (int k = 0; k < 4; k++) acc[mt][nt][k] = 0.f;

#pragma unroll
    for (int s = 0; s < GSTG - 1; s++) {
        gemm_load_stage(As, Bs, A, Bt, m0, n0, K, s, tid);
        CP_COMMIT();
    }

    for (int kb = 0; kb < NCH; kb++) {
        CP_WAIT(GSTG - 2);
        __syncthreads();

        if (kb + GSTG - 1 < NCH)
            gemm_load_stage(As, Bs, A, Bt, m0, n0, K, kb + GSTG - 1, tid);
        CP_COMMIT();

        const uint32_t asb = smem_u32(As + (kb % GSTG) * TILE32);
        const uint32_t bsb = smem_u32(Bs + (kb % GSTG) * TILE32);
#pragma unroll
        for (int ks = 0; ks < 4; ks++) {
            const uint32_t kx = (((uint32_t)(ks * 8) + ko) ^ sw4) * 4u;
            uint32_t af[2][4], bf[8][2], bt4[4];
            ldsm_x4(af[0], asb + a_rb[0] + kx);
            ldsm_x4(af[1], asb + a_rb[1] + kx);
#pragma unroll
            for (int p = 0; p < 4; p++) {
                ldsm_x4(bt4, bsb + b_rb[p] + kx);
                bf[2 * p][0]     = bt4[0];
                bf[2 * p + 1][0] = bt4[1];
                bf[2 * p][1]     = bt4[2];
                bf[2 * p + 1][1] = bt4[3];
            }
#pragma unroll
            for (int mt = 0; mt < 2; mt++)
#pragma unroll
                for (int nt = 0; nt < 8; nt++)
                    mma_tf32(acc[mt][nt], af[mt], bf[nt]);
        }
    }

    // epilogue (unchanged from R8)
#pragma unroll
    for (int mt = 0; mt < 2; mt++) {
        int r0 = m0 + wm * 32 + mt * 16 + g;
#pragma unroll
        for (int nt = 0; nt < 8; nt++) {
            int c = n0 + wn * 64 + nt * 8 + 2 * t;
            float2 b2 = *(const float2*)(bias + c);
            float2 v0 = make_float2(acc[mt][nt][0] + b2.x, acc[mt][nt][1] + b2.y);
            float2 v1 = make_float2(acc[mt][nt][2] + b2.x, acc[mt][nt][3] + b2.y);
            if (mode == 1) {
                v0.x = rn_tf32(v0.x); v0.y = rn_tf32(v0.y);
                v1.x = rn_tf32(v1.x); v1.y = rn_tf32(v1.y);
                if (c < 2048) {
                    int c0p = (c & ~7) | perm8(c & 7);
                    int c1p = (c & ~7) | perm8((c & 7) + 1);
                    C[(size_t)r0 * N + c0p] = v0.x;
                    C[(size_t)r0 * N + c1p] = v0.y;
                    C[(size_t)(r0 + 8) * N + c0p] = v1.x;
                    C[(size_t)(r0 + 8) * N + c1p] = v1.y;
                } else {
                    int h  = (c - 2048) >> 6;
                    int d0 = (c - 2048) & 63;
                    int b0  = r0 >> 11;
                    int tp0 = ((r0 & 2047) & ~7) | perm8(r0 & 7);
                    int tp1 = (((r0 + 8) & 2047) & ~7) | perm8((r0 + 8) & 7);
                    float* vb = vt + ((size_t)(b0 * NH + h) * HD + d0) * TT;
                    vb[tp0]      = v0.x;
                    vb[TT + tp0] = v0.y;
                    vb[tp1]      = v1.x;
                    vb[TT + tp1] = v1.y;
                }
            } else {
                *(float2*)(C + (size_t)r0 * N + c) = v0;
                *(float2*)(C + (size_t)(r0 + 8) * N + c) = v1;
            }
        }
    }
}

// ---------------------------------------------------------------- attention (unchanged from R8)
#define AQ 64
#define AK 64
#define ASTR 72
#define SM_QS 0
#define SM_KS (64*ASTR)
#define SM_VS (SM_KS + 2*64*ASTR)
#define SM_PS (SM_VS + 2*64*ASTR)
#define ATTN_SMEM ((SM_PS + 64*ASTR) * 4)    // 110592 B

__device__ __forceinline__ void attn_load_kv(float* sm, const float* __restrict__ qkv,
                                             const float* __restrict__ vt,
                                             int b, int h, int kt, int buf, int tid)
{
    const float* kbase = qkv + ((size_t)(b * TT + kt * AK)) * C3 + CC + h * HD;
    uint32_t kdst = smem_u32(sm + SM_KS + buf * 64 * ASTR);
#pragma unroll
    for (int i = 0; i < 8; i++) {
        int idx = tid + i * 128;
        int row = idx >> 4, c4 = idx & 15;
        CP_ASYNC16(kdst + (row * ASTR + c4 * 4) * 4, kbase + (size_t)row * C3 + c4 * 4);
    }
    const float* vbase = vt + ((size_t)(b * NH + h) * HD) * TT + kt * AK;
    uint32_t vdst = smem_u32(sm + SM_VS + buf * 64 * ASTR);
#pragma unroll
    for (int i = 0; i < 8; i++) {
        int idx = tid + i * 128;
        int d = idx >> 4, c4 = idx & 15;
        CP_ASYNC16(vdst + (d * ASTR + c4 * 4) * 4, vbase + (size_t)d * TT + c4 * 4);
    }
}

__global__ __launch_bounds__(128, 2) void attn_tc(const float* __restrict__ qkv,
                                                  const float* __restrict__ vt,
                                                  float* __restrict__ y)
{
    extern __shared__ float sm[];
    const int tid = threadIdx.x;
    const int wid = tid >> 5, lane = tid & 31;
    const int g = lane >> 2, t = lane & 3;
    const int qt = gridDim.x - 1 - blockIdx.x;
    const int h  = blockIdx.y;
    const int b  = blockIdx.z;
    const int q0 = qt * AQ;
    const int r0 = wid * 16 + g;

    {
        const float* qbase = qkv + ((size_t)(b * TT + q0)) * C3 + h * HD;
#pragma unroll
        for (int i = 0; i < 8; i++) {
            int idx = tid + i * 128;
            int row = idx >> 4, c4 = idx & 15;
            float4 v = *(const float4*)(qbase + (size_t)row * C3 + c4 * 4);
            v.x *= SCALE; v.y *= SCALE; v.z *= SCALE; v.w *= SCALE;
            *(float4*)(&sm[SM_QS + row * ASTR + c4 * 4]) = v;
        }
    }
    attn_load_kv(sm, qkv, vt, b, h, 0, 0, tid);
    CP_COMMIT();
    __syncthreads();

    uint32_t qf[8][4];
#pragma unroll
    for (int ds = 0; ds < 8; ds++) {
        float2 q0v = *(const float2*)(&sm[SM_QS + r0 * ASTR + ds * 8 + 2 * t]);
        float2 q1v = *(const float2*)(&sm[SM_QS + (r0 + 8) * ASTR + ds * 8 + 2 * t]);
        qf[ds][0] = __float_as_uint(q0v.x);
        qf[ds][1] = __float_as_uint(q1v.x);
        qf[ds][2] = __float_as_uint(q0v.y);
        qf[ds][3] = __float_as_uint(q1v.y);
    }

    float oacc[8][4];
#pragma unroll
    for (int nt = 0; nt < 8; nt++)
#pragma unroll
        for (int k = 0; k < 4; k++) oacc[nt][k] = 0.f;
    float mrow0 = -INFINITY, mrow1 = -INFINITY, lrow0 = 0.f, lrow1 = 0.f;

    const int pp0 = perm8(2 * t), pp1 = perm8(2 * t + 1);

    for (int kt = 0; kt <= qt; kt++) {
        const int buf = kt & 1;
        CP_WAIT(0);
        __syncthreads();
        if (kt < qt) { attn_load_kv(sm, qkv, vt, b, h, kt + 1, buf ^ 1, tid); CP_COMMIT(); }

        const float* ks = sm + SM_KS + buf * 64 * ASTR;
        const float* vs = sm + SM_VS + buf * 64 * ASTR;

        float sacc[8][4];
#pragma unroll
        for (int nt = 0; nt < 8; nt++)
#pragma unroll
            for (int k = 0; k < 4; k++) sacc[nt][k] = 0.f;
#pragma unroll
        for (int ds = 0; ds < 8; ds++) {
            uint32_t bf[8][2];
#pragma unroll
            for (int nt = 0; nt < 8; nt++) {
                float2 kv = *(const float2*)(&ks[(nt * 8 + g) * ASTR + ds * 8 + 2 * t]);
                bf[nt][0] = __float_as_uint(kv.x);
                bf[nt][1] = __float_as_uint(kv.y);
            }
#pragma unroll
            for (int nt = 0; nt < 8; nt++)
                mma_tf32(sacc[nt], qf[ds], bf[nt]);
        }

        if (kt == qt) {
#pragma unroll
            for (int nt = 0; nt < 8; nt++) {
                int c = nt * 8 + 2 * t;
                if (c     > r0)     sacc[nt][0] = -1e30f;
                if (c + 1 > r0)     sacc[nt][1] = -1e30f;
                if (c     > r0 + 8) sacc[nt][2] = -1e30f;
                if (c + 1 > r0 + 8) sacc[nt][3] = -1e30f;
            }
        }

        float tm0 = -INFINITY, tm1 = -INFINITY;
#pragma unroll
        for (int nt = 0; nt < 8; nt++) {
            tm0 = fmaxf(tm0, fmaxf(sacc[nt][0], sacc[nt][1]));
            tm1 = fmaxf(tm1, fmaxf(sacc[nt][2], sacc[nt][3]));
        }
        tm0 = fmaxf(tm0, __shfl_xor_sync(0xffffffffu, tm0, 1));
        tm0 = fmaxf(tm0, __shfl_xor_sync(0xffffffffu, tm0, 2));
        tm1 = fmaxf(tm1, __shfl_xor_sync(0xffffffffu, tm1, 1));
        tm1 = fmaxf(tm1, __shfl_xor_sync(0xffffffffu, tm1, 2));
        float m0 = fmaxf(mrow0, tm0), m1 = fmaxf(mrow1, tm1);
        float a0 = __expf(mrow0 - m0), a1 = __expf(mrow1 - m1);
        mrow0 = m0; mrow1 = m1;
        float rs0 = 0.f, rs1 = 0.f;
#pragma unroll
        for (int nt = 0; nt < 8; nt++) {
            sacc[nt][0] = __expf(sacc[nt][0] - m0); rs0 += sacc[nt][0];
            sacc[nt][1] = __expf(sacc[nt][1] - m0); rs0 += sacc[nt][1];
            sacc[nt][2] = __expf(sacc[nt][2] - m1); rs1 += sacc[nt][2];
            sacc[nt][3] = __expf(sacc[nt][3] - m1); rs1 += sacc[nt][3];
        }
        rs0 += __shfl_xor_sync(0xffffffffu, rs0, 1);
        rs0 += __shfl_xor_sync(0xffffffffu, rs0, 2);
        rs1 += __shfl_xor_sync(0xffffffffu, rs1, 1);
        rs1 += __shfl_xor_sync(0xffffffffu, rs1, 2);
        lrow0 = lrow0 * a0 + rs0;
        lrow1 = lrow1 * a1 + rs1;
#pragma unroll
        for (int nt = 0; nt < 8; nt++) {
            oacc[nt][0] *= a0; oacc[nt][1] *= a0;
            oacc[nt][2] *= a1; oacc[nt][3] *= a1;
        }

#pragma unroll
        for (int nt = 0; nt < 8; nt++) {
            int cb = SM_PS + nt * 8;
            sm[cb + r0 * ASTR + pp0]       = rn_tf32(sacc[nt][0]);
            sm[cb + r0 * ASTR + pp1]       = rn_tf32(sacc[nt][1]);
            sm[cb + (r0 + 8) * ASTR + pp0] = rn_tf32(sacc[nt][2]);
            sm[cb + (r0 + 8) * ASTR + pp1] = rn_tf32(sacc[nt][3]);
        }
        __syncwarp();

#pragma unroll
        for (int kk = 0; kk < 8; kk++) {
            uint32_t af[4];
            float2 p0 = *(const float2*)(&sm[SM_PS + r0 * ASTR + kk * 8 + 2 * t]);
            float2 p1 = *(const float2*)(&sm[SM_PS + (r0 + 8) * ASTR + kk * 8 + 2 * t]);
            af[0] = __float_as_uint(p0.x);
            af[1] = __float_as_uint(p1.x);
            af[2] = __float_as_uint(p0.y);
            af[3] = __float_as_uint(p1.y);
            uint32_t bf[8][2];
#pragma unroll
            for (int nt = 0; nt < 8; nt++) {
                float2 vv = *(const float2*)(&vs[(nt * 8 + g) * ASTR + kk * 8 + 2 * t]);
                bf[nt][0] = __float_as_uint(vv.x);
                bf[nt][1] = __float_as_uint(vv.y);
            }
#pragma unroll
            for (int nt = 0; nt < 8; nt++)
                mma_tf32(oacc[nt], af, bf[nt]);
        }
    }

    float inv0 = 1.0f / lrow0, inv1 = 1.0f / lrow1;
    float* ybase = y + ((size_t)(b * TT + q0)) * CC + h * HD;
#pragma unroll
    for (int nt = 0; nt < 8; nt++) {
        int cb = nt * 8;
        ybase[(size_t)r0 * CC + cb + pp0]       = rn_tf32(oacc[nt][0] * inv0);
        ybase[(size_t)r0 * CC + cb + pp1]       = rn_tf32(oacc[nt][1] * inv0);
        ybase[(size_t)(r0 + 8) * CC + cb + pp0] = rn_tf32(oacc[nt][2] * inv1);
        ybase[(size_t)(r0 + 8) * CC + cb + pp1] = rn_tf32(oacc[nt][3] * inv1);
    }
}

// ---------------------------------------------------------------- launch
extern "C" void kernel_launch(void* const* d_in, const int* in_sizes, int n_in,
                              void* d_out, int out_size)
{
    const float* x      = (const float*)d_in[0];
    const float* w_attn = (const float*)d_in[1];
    const float* b_attn = (const float*)d_in[2];
    const float* w_proj = (const float*)d_in[3];
    const float* b_proj = (const float*)d_in[4];
    float* out = (float*)d_out;

    float *qkv, *vt, *yb, *xp, *waT, *wpT;
    cudaGetSymbolAddress((void**)&qkv, g_qkv);
    cudaGetSymbolAddress((void**)&vt,  g_vt);
    cudaGetSymbolAddress((void**)&yb,  g_y);
    cudaGetSymbolAddress((void**)&xp,  g_xp);
    cudaGetSymbolAddress((void**)&waT, g_waT);
    cudaGetSymbolAddress((void**)&wpT, g_wpT);

    cudaFuncSetAttribute(gemm_tf32, cudaFuncAttributeMaxDynamicSharedMemorySize, GEMM_SMEM);
    cudaFuncSetAttribute(attn_tc,   cudaFuncAttributeMaxDynamicSharedMemorySize, ATTN_SMEM);

    round_perm_kernel<<<(BT * CC) / (256 * 8), 256>>>(x, xp);
    transpose_perm_kernel<<<dim3(C3 / 32, CC / 32), dim3(32, 8)>>>(w_attn, waT, CC, C3);
    transpose_perm_kernel<<<dim3(CC / 32, CC / 32), dim3(32, 8)>>>(w_proj, wpT, CC, CC);

    gemm_tf32<<<dim3(C3 / GBN, BT / GBM), 256, GEMM_SMEM>>>(xp, waT, b_attn, qkv, vt,
                                                            BT, C3, CC, 1);

    attn_tc<<<dim3(TT / AQ, NH, BB), 128, ATTN_SMEM>>>(qkv, vt, yb);

    gemm_tf32<<<dim3(CC / GBN, BT / GBM), 256, GEMM_SMEM>>>(yb, wpT, b_proj, out, vt,
                                                            BT, CC, CC, 0);
}

// round 10
// speedup vs baseline: 1.1311x; 1.0542x over previous
#include <cuda_runtime.h>
#include <cstdint>
#include <cmath>

// ---------------------------------------------------------------- constants
#define BB   2
#define TT   2048
#define CC   1024
#define NH   16
#define HD   64
#define BT   (BB*TT)          // 4096
#define C3   (3*CC)           // 3072
#define SCALE 0.125f

// ---------------------------------------------------------------- scratch
__device__ float g_qkv[(size_t)BT * C3];        // Q,K regions (cols<2048), col-permuted
__device__ float g_vt [(size_t)BB*NH*HD*TT];    // V transposed [b,h,d,token], tok-permuted
__device__ float g_y  [(size_t)BT * CC];        // attention out, col-permuted, tf32
__device__ float g_xp [(size_t)BT * CC];        // x rounded+col-permuted
__device__ float g_waT[(size_t)C3 * CC];        // w_attn^T [N,K], K-permuted, tf32
__device__ float g_wpT[(size_t)CC * CC];        // w_proj^T [N,K], K-permuted, tf32

// ---------------------------------------------------------------- utils
__device__ __forceinline__ uint32_t smem_u32(const void* p) {
    uint32_t a;
    asm("{ .reg .u64 t; cvta.to.shared.u64 t, %1; cvt.u32.u64 %0, t; }" : "=r"(a) : "l"(p));
    return a;
}
__device__ __forceinline__ float rn_tf32(float x) {
    uint32_t r;
    asm("cvt.rna.tf32.f32 %0, %1;" : "=r"(r) : "f"(x));
    return __uint_as_float(r);
}
#define CP_ASYNC16(dst, src) \
    asm volatile("cp.async.cg.shared.global [%0], [%1], 16;\n" :: "r"(dst), "l"(src))
#define CP_COMMIT() asm volatile("cp.async.commit_group;" ::: "memory")
#define CP_WAIT(n)  asm volatile("cp.async.wait_group %0;" :: "n"(n) : "memory")

__device__ __forceinline__ void mma_tf32(float* c, const uint32_t* a, const uint32_t* b) {
    asm volatile(
        "mma.sync.aligned.m16n8k8.row.col.f32.tf32.tf32.f32 "
        "{%0,%1,%2,%3}, {%4,%5,%6,%7}, {%8,%9}, {%0,%1,%2,%3};"
        : "+f"(c[0]), "+f"(c[1]), "+f"(c[2]), "+f"(c[3])
        : "r"(a[0]), "r"(a[1]), "r"(a[2]), "r"(a[3]), "r"(b[0]), "r"(b[1]));
}
__device__ __forceinline__ void ldsm_x4(uint32_t* r, uint32_t addr) {
    asm volatile("ldmatrix.sync.aligned.m8n8.x4.shared.b16 {%0,%1,%2,%3}, [%4];"
        : "=r"(r[0]), "=r"(r[1]), "=r"(r[2]), "=r"(r[3]) : "r"(addr));
}
// position of natural index u within its 8-group: [0,4,1,5,2,6,3,7]
__device__ __forceinline__ int perm8(int u) { return u < 4 ? 2 * u : 2 * u - 7; }

// ---------------------------------------------------------------- prep
__global__ void round_perm_kernel(const float* __restrict__ in, float* __restrict__ out) {
    size_t i = ((size_t)blockIdx.x * blockDim.x + threadIdx.x) * 8;
    float4 a = *(const float4*)(in + i);
    float4 b = *(const float4*)(in + i + 4);
    float4 o0 = make_float4(rn_tf32(a.x), rn_tf32(b.x), rn_tf32(a.y), rn_tf32(b.y));
    float4 o1 = make_float4(rn_tf32(a.z), rn_tf32(b.z), rn_tf32(a.w), rn_tf32(b.w));
    *(float4*)(out + i)     = o0;
    *(float4*)(out + i + 4) = o1;
}

__global__ void transpose_perm_kernel(const float* __restrict__ in, float* __restrict__ out,
                                      int K, int N) {
    __shared__ float tsm[32][33];
    int k0 = blockIdx.y * 32, n0 = blockIdx.x * 32;
    int tx = threadIdx.x, ty = threadIdx.y;     // 32 x 8
#pragma unroll
    for (int i = 0; i < 32; i += 8)
        tsm[ty + i][tx] = in[(size_t)(k0 + ty + i) * N + n0 + tx];
    __syncthreads();
    int kk = (tx & ~7) | (((tx & 7) >> 1) + (tx & 1) * 4);   // gather
#pragma unroll
    for (int i = 0; i < 32; i += 8)
        out[(size_t)(n0 + ty + i) * K + k0 + tx] = rn_tf32(tsm[kk][ty + i]);
}

// ---------------------------------------------------------------- tf32 GEMM
#define GBM 128
#define GBN 128
#define GBK 32
#define GSTG 3
#define TILE32 (128 * 32)
#define GEMM_SMEM (GSTG * 2 * TILE32 * 4)    // 98304 B

__global__ __launch_bounds__(256, 2) void gemm_tf32(
    const float* __restrict__ A, const float* __restrict__ Bt,
    const float* __restrict__ bias, float* __restrict__ C,
    float* __restrict__ vt, int M, int N, int K, int mode)
{
    extern __shared__ float smf[];
    float* As = smf;
    float* Bs = smf + GSTG * TILE32;

    const int tid = threadIdx.x, wid = tid >> 5, lane = tid & 31;
    const int g = lane >> 2, t = lane & 3;
    const int wm = wid & 3, wn = wid >> 2;
    const int m0 = blockIdx.y * GBM, n0 = blockIdx.x * GBN;
    const int NCH = K / GBK;

    // hoisted staging geometry: smem offsets constant, global offsets += GBK
    uint32_t soff[4], agf[4], bgf[4];
#pragma unroll
    for (int i = 0; i < 4; i++) {
        int idx = tid + i * 256, row = idx >> 3, c4 = idx & 7;
        soff[i] = (uint32_t)(row * 32 + ((c4 * 4) ^ (4 * (row & 7)))) * 4u;
        agf[i]  = (uint32_t)((m0 + row) * K + c4 * 4);
        bgf[i]  = (uint32_t)((n0 + row) * K + c4 * 4);
    }
    const uint32_t asb0 = smem_u32(As), bsb0 = smem_u32(Bs);
    int s_fill = 0;

    // ldmatrix per-lane geometry
    const int lq = lane >> 3, li = lane & 7;
    const uint32_t sw4 = 4u * (uint32_t)li;
    const uint32_t ko  = (uint32_t)((lq >> 1) * 4);
    uint32_t a_rb[2], b_rb[4];
#pragma unroll
    for (int mt = 0; mt < 2; mt++)
        a_rb[mt] = (uint32_t)(wm * 32 + mt * 16 + (lq & 1) * 8 + li) * 128u;
#pragma unroll
    for (int p = 0; p < 4; p++)
        b_rb[p] = (uint32_t)(wn * 64 + p * 16 + (lq & 1) * 8 + li) * 128u;

    float acc[2][8][4];
#pragma unroll
    for (int mt = 0; mt < 2; mt++)
#pragma unroll
        for (int nt = 0; nt < 8; nt++)
#pragma unroll
            for (int k = 0; k < 4; k++) acc[mt][nt][k] = 0.f;

#pragma unroll
    for (int s = 0; s < GSTG - 1; s++) {
        uint32_t ab = asb0 + s_fill * (TILE32 * 4), bb = bsb0 + s_fill * (TILE32 * 4);
#pragma unroll
        for (int i = 0; i < 4; i++) {
            CP_ASYNC16(ab + soff[i], A  + agf[i]);
            CP_ASYNC16(bb + soff[i], Bt + bgf[i]);
        }
#pragma unroll
        for (int i = 0; i < 4; i++) { agf[i] += GBK; bgf[i] += GBK; }
        if (++s_fill == GSTG) s_fill = 0;
        CP_COMMIT();
    }

    int s_use = 0;
    for (int kb = 0; kb < NCH; kb++) {
        CP_WAIT(GSTG - 2);
        __syncthreads();

        if (kb + GSTG - 1 < NCH) {
            uint32_t ab = asb0 + s_fill * (TILE32 * 4), bb = bsb0 + s_fill * (TILE32 * 4);
#pragma unroll
            for (int i = 0; i < 4; i++) {
                CP_ASYNC16(ab + soff[i], A  + agf[i]);
                CP_ASYNC16(bb + soff[i], Bt + bgf[i]);
            }
#pragma unroll
            for (int i = 0; i < 4; i++) { agf[i] += GBK; bgf[i] += GBK; }
            if (++s_fill == GSTG) s_fill = 0;
        }
        CP_COMMIT();

        const uint32_t asb = asb0 + s_use * (TILE32 * 4);
        const uint32_t bsb = bsb0 + s_use * (TILE32 * 4);
        if (++s_use == GSTG) s_use = 0;
#pragma unroll
        for (int ks = 0; ks < 4; ks++) {
            const uint32_t kx = (((uint32_t)(ks * 8) + ko) ^ sw4) * 4u;
            uint32_t af[2][4], bf[8][2], bt4[4];
            ldsm_x4(af[0], asb + a_rb[0] + kx);
            ldsm_x4(af[1], asb + a_rb[1] + kx);
#pragma unroll
            for (int p = 0; p < 4; p++) {
                ldsm_x4(bt4, bsb + b_rb[p] + kx);
                bf[2 * p][0]     = bt4[0];
                bf[2 * p + 1][0] = bt4[1];
                bf[2 * p][1]     = bt4[2];
                bf[2 * p + 1][1] = bt4[3];
            }
#pragma unroll
            for (int mt = 0; mt < 2; mt++)
#pragma unroll
                for (int nt = 0; nt < 8; nt++)
                    mma_tf32(acc[mt][nt], af[mt], bf[nt]);
        }
    }

    // epilogue (unchanged)
#pragma unroll
    for (int mt = 0; mt < 2; mt++) {
        int r0 = m0 + wm * 32 + mt * 16 + g;
#pragma unroll
        for (int nt = 0; nt < 8; nt++) {
            int c = n0 + wn * 64 + nt * 8 + 2 * t;
            float2 b2 = *(const float2*)(bias + c);
            float2 v0 = make_float2(acc[mt][nt][0] + b2.x, acc[mt][nt][1] + b2.y);
            float2 v1 = make_float2(acc[mt][nt][2] + b2.x, acc[mt][nt][3] + b2.y);
            if (mode == 1) {
                v0.x = rn_tf32(v0.x); v0.y = rn_tf32(v0.y);
                v1.x = rn_tf32(v1.x); v1.y = rn_tf32(v1.y);
                if (c < 2048) {
                    int c0p = (c & ~7) | perm8(c & 7);
                    int c1p = (c & ~7) | perm8((c & 7) + 1);
                    C[(size_t)r0 * N + c0p] = v0.x;
                    C[(size_t)r0 * N + c1p] = v0.y;
                    C[(size_t)(r0 + 8) * N + c0p] = v1.x;
                    C[(size_t)(r0 + 8) * N + c1p] = v1.y;
                } else {
                    int h  = (c - 2048) >> 6;
                    int d0 = (c - 2048) & 63;
                    int b0  = r0 >> 11;
                    int tp0 = ((r0 & 2047) & ~7) | perm8(r0 & 7);
                    int tp1 = (((r0 + 8) & 2047) & ~7) | perm8((r0 + 8) & 7);
                    float* vb = vt + ((size_t)(b0 * NH + h) * HD + d0) * TT;
                    vb[tp0]      = v0.x;
                    vb[TT + tp0] = v0.y;
                    vb[tp1]      = v1.x;
                    vb[TT + tp1] = v1.y;
                }
            } else {
                *(float2*)(C + (size_t)r0 * N + c) = v0;
                *(float2*)(C + (size_t)(r0 + 8) * N + c) = v1;
            }
        }
    }
}

// ---------------------------------------------------------------- attention (ldmatrix)
// All tiles 64x64, unpadded rows (64 floats) with GEMM XOR swizzle ^4*(row&7).
// Q [m][k-perm], K [n][k-perm], V [n][k-perm] (from vt), P [m][k-perm].
#define AQ 64
#define AK 64
#define SM_QS 0
#define SM_KS 4096
#define SM_VS (SM_KS + 2*4096)
#define SM_PS (SM_VS + 2*4096)
#define ATTN_SMEM ((SM_PS + 4096) * 4)       // 98304 B

__global__ __launch_bounds__(128, 2) void attn_tc(const float* __restrict__ qkv,
                                                  const float* __restrict__ vt,
                                                  float* __restrict__ y)
{
    extern __shared__ float sm[];
    const int tid = threadIdx.x;
    const int wid = tid >> 5, lane = tid & 31;
    const int g = lane >> 2, t = lane & 3;
    const int qt = gridDim.x - 1 - blockIdx.x;
    const int h  = blockIdx.y;
    const int b  = blockIdx.z;
    const int q0 = qt * AQ;
    const int r0 = wid * 16 + g;
    const uint32_t smb = smem_u32(sm);

    // ldmatrix lane geometry
    const int lq = lane >> 3, li = lane & 7;
    const uint32_t sw4 = 4u * (uint32_t)li;
    const uint32_t ko  = (uint32_t)((lq >> 1) * 4);
    const uint32_t rq  = (uint32_t)((lq & 1) * 8 + li);
    const uint32_t q_rb = (uint32_t)(wid * 16 + rq) * 256u;   // Q/P row base (bytes)
    uint32_t n_rb[4];
#pragma unroll
    for (int p = 0; p < 4; p++) n_rb[p] = (uint32_t)(p * 16 + rq) * 256u;

    // hoisted staging geometry (K and V tiles share shape)
    uint32_t st_off[8], kg[8], vg[8];
#pragma unroll
    for (int i = 0; i < 8; i++) {
        int idx = tid + i * 128, row = idx >> 4, c4 = idx & 15;
        st_off[i] = (uint32_t)(row * 64 + ((c4 * 4) ^ (4 * (row & 7)))) * 4u;
        kg[i] = (uint32_t)(row * C3 + c4 * 4);
        vg[i] = (uint32_t)(row * TT + c4 * 4);
    }
    const float* kb0 = qkv + ((size_t)(b * TT)) * C3 + CC + h * HD;
    const float* vb0 = vt + ((size_t)(b * NH + h) * HD) * TT;

    // stage Q (scaled, swizzled)
    {
        const float* qbase = qkv + ((size_t)(b * TT + q0)) * C3 + h * HD;
#pragma unroll
        for (int i = 0; i < 8; i++) {
            int idx = tid + i * 128, row = idx >> 4, c4 = idx & 15;
            float4 v = *(const float4*)(qbase + (size_t)row * C3 + c4 * 4);
            v.x *= SCALE; v.y *= SCALE; v.z *= SCALE; v.w *= SCALE;
            *(float4*)(&sm[SM_QS + row * 64 + ((c4 * 4) ^ (4 * (row & 7)))]) = v;
        }
    }
    // prologue K/V tile 0
    {
        uint32_t kd = smb + SM_KS * 4, vd = smb + SM_VS * 4;
#pragma unroll
        for (int i = 0; i < 8; i++) {
            CP_ASYNC16(kd + st_off[i], kb0 + kg[i]);
            CP_ASYNC16(vd + st_off[i], vb0 + vg[i]);
        }
    }
    CP_COMMIT();
    __syncthreads();

    // Q fragments once (8 LDSM.x4)
    uint32_t qf[8][4];
#pragma unroll
    for (int ds = 0; ds < 8; ds++)
        ldsm_x4(qf[ds], smb + SM_QS * 4 + q_rb + ((((uint32_t)(ds * 8) + ko) ^ sw4) << 2));

    float oacc[8][4];
#pragma unroll
    for (int nt = 0; nt < 8; nt++)
#pragma unroll
        for (int k = 0; k < 4; k++) oacc[nt][k] = 0.f;
    float mrow0 = -INFINITY, mrow1 = -INFINITY, lrow0 = 0.f, lrow1 = 0.f;

    const int pp0 = perm8(2 * t), pp1 = perm8(2 * t + 1);
    const int sx = 4 * g;                         // P store swizzle (row&7 == g)
    const int ps0 = SM_PS + r0 * 64, ps1 = SM_PS + (r0 + 8) * 64;

    for (int kt = 0; kt <= qt; kt++) {
        const int buf = kt & 1;
        CP_WAIT(0);
        __syncthreads();
        if (kt < qt) {
            uint32_t kd = smb + (SM_KS + (buf ^ 1) * 4096) * 4;
            uint32_t vd = smb + (SM_VS + (buf ^ 1) * 4096) * 4;
            const float* kp = kb0 + (size_t)(kt + 1) * 64 * C3;
            const float* vp = vb0 + (kt + 1) * 64;
#pragma unroll
            for (int i = 0; i < 8; i++) {
                CP_ASYNC16(kd + st_off[i], kp + kg[i]);
                CP_ASYNC16(vd + st_off[i], vp + vg[i]);
            }
        }
        CP_COMMIT();

        const uint32_t ksb = smb + (SM_KS + buf * 4096) * 4;
        const uint32_t vsb = smb + (SM_VS + buf * 4096) * 4;

        // S = Q K^T  (4 LDSM.x4 per ds)
        float sacc[8][4];
#pragma unroll
        for (int nt = 0; nt < 8; nt++)
#pragma unroll
            for (int k = 0; k < 4; k++) sacc[nt][k] = 0.f;
#pragma unroll
        for (int ds = 0; ds < 8; ds++) {
            const uint32_t kx = (((uint32_t)(ds * 8) + ko) ^ sw4) << 2;
            uint32_t bf[8][2], bt4[4];
#pragma unroll
            for (int p = 0; p < 4; p++) {
                ldsm_x4(bt4, ksb + n_rb[p] + kx);
                bf[2 * p][0]     = bt4[0];
                bf[2 * p + 1][0] = bt4[1];
                bf[2 * p][1]     = bt4[2];
                bf[2 * p + 1][1] = bt4[3];
            }
#pragma unroll
            for (int nt = 0; nt < 8; nt++)
                mma_tf32(sacc[nt], qf[ds], bf[nt]);
        }

        if (kt == qt) {
#pragma unroll
            for (int nt = 0; nt < 8; nt++) {
                int c = nt * 8 + 2 * t;
                if (c     > r0)     sacc[nt][0] = -1e30f;
                if (c + 1 > r0)     sacc[nt][1] = -1e30f;
                if (c     > r0 + 8) sacc[nt][2] = -1e30f;
                if (c + 1 > r0 + 8) sacc[nt][3] = -1e30f;
            }
        }

        // online softmax
        float tm0 = -INFINITY, tm1 = -INFINITY;
#pragma unroll
        for (int nt = 0; nt < 8; nt++) {
            tm0 = fmaxf(tm0, fmaxf(sacc[nt][0], sacc[nt][1]));
            tm1 = fmaxf(tm1, fmaxf(sacc[nt][2], sacc[nt][3]));
        }
        tm0 = fmaxf(tm0, __shfl_xor_sync(0xffffffffu, tm0, 1));
        tm0 = fmaxf(tm0, __shfl_xor_sync(0xffffffffu, tm0, 2));
        tm1 = fmaxf(tm1, __shfl_xor_sync(0xffffffffu, tm1, 1));
        tm1 = fmaxf(tm1, __shfl_xor_sync(0xffffffffu, tm1, 2));
        float m0 = fmaxf(mrow0, tm0), m1 = fmaxf(mrow1, tm1);
        float a0 = __expf(mrow0 - m0), a1 = __expf(mrow1 - m1);
        mrow0 = m0; mrow1 = m1;
        float rs0 = 0.f, rs1 = 0.f;
#pragma unroll
        for (int nt = 0; nt < 8; nt++) {
            sacc[nt][0] = __expf(sacc[nt][0] - m0); rs0 += sacc[nt][0];
            sacc[nt][1] = __expf(sacc[nt][1] - m0); rs0 += sacc[nt][1];
            sacc[nt][2] = __expf(sacc[nt][2] - m1); rs1 += sacc[nt][2];
            sacc[nt][3] = __expf(sacc[nt][3] - m1); rs1 += sacc[nt][3];
        }
        rs0 += __shfl_xor_sync(0xffffffffu, rs0, 1);
        rs0 += __shfl_xor_sync(0xffffffffu, rs0, 2);
        rs1 += __shfl_xor_sync(0xffffffffu, rs1, 1);
        rs1 += __shfl_xor_sync(0xffffffffu, rs1, 2);
        lrow0 = lrow0 * a0 + rs0;
        lrow1 = lrow1 * a1 + rs1;
#pragma unroll
        for (int nt = 0; nt < 8; nt++) {
            oacc[nt][0] *= a0; oacc[nt][1] *= a0;
            oacc[nt][2] *= a1; oacc[nt][3] *= a1;
        }

        // stage P (token-permuted + swizzled)
#pragma unroll
        for (int nt = 0; nt < 8; nt++) {
            int e0 = ((nt * 8 + (pp0 & 4)) ^ sx) + (pp0 & 3);
            int e1 = ((nt * 8 + (pp1 & 4)) ^ sx) + (pp1 & 3);
            sm[ps0 + e0] = rn_tf32(sacc[nt][0]);
            sm[ps0 + e1] = rn_tf32(sacc[nt][1]);
            sm[ps1 + e0] = rn_tf32(sacc[nt][2]);
            sm[ps1 + e1] = rn_tf32(sacc[nt][3]);
        }
        __syncwarp();

        // O += P @ V  (1 + 4 LDSM.x4 per kk)
#pragma unroll
        for (int kk = 0; kk < 8; kk++) {
            const uint32_t kx = (((uint32_t)(kk * 8) + ko) ^ sw4) << 2;
            uint32_t af[4], bf[8][2], bt4[4];
            ldsm_x4(af, smb + SM_PS * 4 + q_rb + kx);
#pragma unroll
            for (int p = 0; p < 4; p++) {
                ldsm_x4(bt4, vsb + n_rb[p] + kx);
                bf[2 * p][0]     = bt4[0];
                bf[2 * p + 1][0] = bt4[1];
                bf[2 * p][1]     = bt4[2];
                bf[2 * p + 1][1] = bt4[3];
            }
#pragma unroll
            for (int nt = 0; nt < 8; nt++)
                mma_tf32(oacc[nt], af, bf[nt]);
        }
    }

    // normalize + store, col-permuted (feeds proj GEMM's permuted A)
    float inv0 = 1.0f / lrow0, inv1 = 1.0f / lrow1;
    float* ybase = y + ((size_t)(b * TT + q0)) * CC + h * HD;
#pragma unroll
    for (int nt = 0; nt < 8; nt++) {
        int cb = nt * 8;
        ybase[(size_t)r0 * CC + cb + pp0]       = rn_tf32(oacc[nt][0] * inv0);
        ybase[(size_t)r0 * CC + cb + pp1]       = rn_tf32(oacc[nt][1] * inv0);
        ybase[(size_t)(r0 + 8) * CC + cb + pp0] = rn_tf32(oacc[nt][2] * inv1);
        ybase[(size_t)(r0 + 8) * CC + cb + pp1] = rn_tf32(oacc[nt][3] * inv1);
    }
}

// ---------------------------------------------------------------- launch
extern "C" void kernel_launch(void* const* d_in, const int* in_sizes, int n_in,
                              void* d_out, int out_size)
{
    const float* x      = (const float*)d_in[0];
    const float* w_attn = (const float*)d_in[1];
    const float* b_attn = (const float*)d_in[2];
    const float* w_proj = (const float*)d_in[3];
    const float* b_proj = (const float*)d_in[4];
    float* out = (float*)d_out;

    float *qkv, *vt, *yb, *xp, *waT, *wpT;
    cudaGetSymbolAddress((void**)&qkv, g_qkv);
    cudaGetSymbolAddress((void**)&vt,  g_vt);
    cudaGetSymbolAddress((void**)&yb,  g_y);
    cudaGetSymbolAddress((void**)&xp,  g_xp);
    cudaGetSymbolAddress((void**)&waT, g_waT);
    cudaGetSymbolAddress((void**)&wpT, g_wpT);

    cudaFuncSetAttribute(gemm_tf32, cudaFuncAttributeMaxDynamicSharedMemorySize, GEMM_SMEM);
    cudaFuncSetAttribute(attn_tc,   cudaFuncAttributeMaxDynamicSharedMemorySize, ATTN_SMEM);

    round_perm_kernel<<<(BT * CC) / (256 * 8), 256>>>(x, xp);
    transpose_perm_kernel<<<dim3(C3 / 32, CC / 32), dim3(32, 8)>>>(w_attn, waT, CC, C3);
    transpose_perm_kernel<<<dim3(CC / 32, CC / 32), dim3(32, 8)>>>(w_proj, wpT, CC, CC);

    gemm_tf32<<<dim3(C3 / GBN, BT / GBM), 256, GEMM_SMEM>>>(xp, waT, b_attn, qkv, vt,
                                                            BT, C3, CC, 1);

    attn_tc<<<dim3(TT / AQ, NH, BB), 128, ATTN_SMEM>>>(qkv, vt, yb);

    gemm_tf32<<<dim3(CC / GBN, BT / GBM), 256, GEMM_SMEM>>>(yb, wpT, b_proj, out, vt,
                                                            BT, CC, CC, 0);
}

// round 11
// speedup vs baseline: 1.1839x; 1.0467x over previous
#include <cuda_runtime.h>
#include <cstdint>
#include <cmath>

// ---------------------------------------------------------------- constants
#define BB   2
#define TT   2048
#define CC   1024
#define NH   16
#define HD   64
#define BT   (BB*TT)          // 4096
#define C3   (3*CC)           // 3072
#define SCALE 0.125f

// ---------------------------------------------------------------- scratch
__device__ float g_qkv[(size_t)BT * C3];        // Q,K regions (cols<2048), col-permuted
__device__ float g_vt [(size_t)BB*NH*HD*TT];    // V transposed [b,h,d,token], tok pos_v-permuted
__device__ float g_y  [(size_t)BT * CC];        // attention out, col-permuted, tf32
__device__ float g_xp [(size_t)BT * CC];        // x rounded+col-permuted
__device__ float g_waT[(size_t)C3 * CC];        // w_attn^T [N,K], K-permuted, tf32
__device__ float g_wpT[(size_t)CC * CC];        // w_proj^T [N,K], K-permuted, tf32

// ---------------------------------------------------------------- utils
__device__ __forceinline__ uint32_t smem_u32(const void* p) {
    uint32_t a;
    asm("{ .reg .u64 t; cvta.to.shared.u64 t, %1; cvt.u32.u64 %0, t; }" : "=r"(a) : "l"(p));
    return a;
}
__device__ __forceinline__ float rn_tf32(float x) {
    uint32_t r;
    asm("cvt.rna.tf32.f32 %0, %1;" : "=r"(r) : "f"(x));
    return __uint_as_float(r);
}
#define CP_ASYNC16(dst, src) \
    asm volatile("cp.async.cg.shared.global [%0], [%1], 16;\n" :: "r"(dst), "l"(src))
#define CP_COMMIT() asm volatile("cp.async.commit_group;" ::: "memory")
#define CP_WAIT(n)  asm volatile("cp.async.wait_group %0;" :: "n"(n) : "memory")

__device__ __forceinline__ void mma_tf32(float* c, const uint32_t* a, const uint32_t* b) {
    asm volatile(
        "mma.sync.aligned.m16n8k8.row.col.f32.tf32.tf32.f32 "
        "{%0,%1,%2,%3}, {%4,%5,%6,%7}, {%8,%9}, {%0,%1,%2,%3};"
        : "+f"(c[0]), "+f"(c[1]), "+f"(c[2]), "+f"(c[3])
        : "r"(a[0]), "r"(a[1]), "r"(a[2]), "r"(a[3]), "r"(b[0]), "r"(b[1]));
}
__device__ __forceinline__ void ldsm_x4(uint32_t* r, uint32_t addr) {
    asm volatile("ldmatrix.sync.aligned.m8n8.x4.shared.b16 {%0,%1,%2,%3}, [%4];"
        : "=r"(r[0]), "=r"(r[1]), "=r"(r[2]), "=r"(r[3]) : "r"(addr));
}
// position of natural index u within its 8-group under gather [0,4,1,5,2,6,3,7]
__device__ __forceinline__ int perm8(int u) { return u < 4 ? 2 * u : 2 * u - 7; }
// V-token permutation: position of natural u under gather_v [0,2,4,6,1,3,5,7]
__device__ __forceinline__ int posv(int u) { return (u >> 1) + (u & 1) * 4; }

// ---------------------------------------------------------------- prep
__global__ void round_perm_kernel(const float* __restrict__ in, float* __restrict__ out) {
    size_t i = ((size_t)blockIdx.x * blockDim.x + threadIdx.x) * 8;
    float4 a = *(const float4*)(in + i);
    float4 b = *(const float4*)(in + i + 4);
    float4 o0 = make_float4(rn_tf32(a.x), rn_tf32(b.x), rn_tf32(a.y), rn_tf32(b.y));
    float4 o1 = make_float4(rn_tf32(a.z), rn_tf32(b.z), rn_tf32(a.w), rn_tf32(b.w));
    *(float4*)(out + i)     = o0;
    *(float4*)(out + i + 4) = o1;
}

__global__ void transpose_perm_kernel(const float* __restrict__ in, float* __restrict__ out,
                                      int K, int N) {
    __shared__ float tsm[32][33];
    int k0 = blockIdx.y * 32, n0 = blockIdx.x * 32;
    int tx = threadIdx.x, ty = threadIdx.y;     // 32 x 8
#pragma unroll
    for (int i = 0; i < 32; i += 8)
        tsm[ty + i][tx] = in[(size_t)(k0 + ty + i) * N + n0 + tx];
    __syncthreads();
    int kk = (tx & ~7) | (((tx & 7) >> 1) + (tx & 1) * 4);   // gather
#pragma unroll
    for (int i = 0; i < 32; i += 8)
        out[(size_t)(n0 + ty + i) * K + k0 + tx] = rn_tf32(tsm[kk][ty + i]);
}

// ---------------------------------------------------------------- tf32 GEMM
#define GBM 128
#define GBN 128
#define GBK 32
#define GSTG 3
#define TILE32 (128 * 32)
#define GEMM_SMEM (GSTG * 2 * TILE32 * 4)    // 98304 B

__global__ __launch_bounds__(256, 2) void gemm_tf32(
    const float* __restrict__ A, const float* __restrict__ Bt,
    const float* __restrict__ bias, float* __restrict__ C,
    float* __restrict__ vt, int M, int N, int K, int mode)
{
    extern __shared__ float smf[];
    float* As = smf;
    float* Bs = smf + GSTG * TILE32;

    const int tid = threadIdx.x, wid = tid >> 5, lane = tid & 31;
    const int g = lane >> 2, t = lane & 3;
    const int wm = wid & 3, wn = wid >> 2;
    const int m0 = blockIdx.y * GBM, n0 = blockIdx.x * GBN;
    const int NCH = K / GBK;

    // hoisted staging geometry
    uint32_t soff[4], agf[4], bgf[4];
#pragma unroll
    for (int i = 0; i < 4; i++) {
        int idx = tid + i * 256, row = idx >> 3, c4 = idx & 7;
        soff[i] = (uint32_t)(row * 32 + ((c4 * 4) ^ (4 * (row & 7)))) * 4u;
        agf[i]  = (uint32_t)((m0 + row) * K + c4 * 4);
        bgf[i]  = (uint32_t)((n0 + row) * K + c4 * 4);
    }
    const uint32_t asb0 = smem_u32(As), bsb0 = smem_u32(Bs);
    int s_fill = 0;

    // ldmatrix per-lane geometry
    const int lq = lane >> 3, li = lane & 7;
    const uint32_t sw4 = 4u * (uint32_t)li;
    const uint32_t ko  = (uint32_t)((lq >> 1) * 4);
    uint32_t a_rb[2], b_rb[4];
#pragma unroll
    for (int mt = 0; mt < 2; mt++)
        a_rb[mt] = (uint32_t)(wm * 32 + mt * 16 + (lq & 1) * 8 + li) * 128u;
#pragma unroll
    for (int p = 0; p < 4; p++)
        b_rb[p] = (uint32_t)(wn * 64 + p * 16 + (lq & 1) * 8 + li) * 128u;

    float acc[2][8][4];
#pragma unroll
    for (int mt = 0; mt < 2; mt++)
#pragma unroll
        for (int nt = 0; nt < 8; nt++)
#pragma unroll
            for (int k = 0; k < 4; k++) acc[mt][nt][k] = 0.f;

#pragma unroll
    for (int s = 0; s < GSTG - 1; s++) {
        uint32_t ab = asb0 + s_fill * (TILE32 * 4), bb = bsb0 + s_fill * (TILE32 * 4);
#pragma unroll
        for (int i = 0; i < 4; i++) {
            CP_ASYNC16(ab + soff[i], A  + agf[i]);
            CP_ASYNC16(bb + soff[i], Bt + bgf[i]);
        }
#pragma unroll
        for (int i = 0; i < 4; i++) { agf[i] += GBK; bgf[i] += GBK; }
        if (++s_fill == GSTG) s_fill = 0;
        CP_COMMIT();
    }

    int s_use = 0;
    for (int kb = 0; kb < NCH; kb++) {
        CP_WAIT(GSTG - 2);
        __syncthreads();

        if (kb + GSTG - 1 < NCH) {
            uint32_t ab = asb0 + s_fill * (TILE32 * 4), bb = bsb0 + s_fill * (TILE32 * 4);
#pragma unroll
            for (int i = 0; i < 4; i++) {
                CP_ASYNC16(ab + soff[i], A  + agf[i]);
                CP_ASYNC16(bb + soff[i], Bt + bgf[i]);
            }
#pragma unroll
            for (int i = 0; i < 4; i++) { agf[i] += GBK; bgf[i] += GBK; }
            if (++s_fill == GSTG) s_fill = 0;
        }
        CP_COMMIT();

        const uint32_t asb = asb0 + s_use * (TILE32 * 4);
        const uint32_t bsb = bsb0 + s_use * (TILE32 * 4);
        if (++s_use == GSTG) s_use = 0;
#pragma unroll
        for (int ks = 0; ks < 4; ks++) {
            const uint32_t kx = (((uint32_t)(ks * 8) + ko) ^ sw4) * 4u;
            uint32_t af[2][4], bf[8][2], bt4[4];
            ldsm_x4(af[0], asb + a_rb[0] + kx);
            ldsm_x4(af[1], asb + a_rb[1] + kx);
#pragma unroll
            for (int p = 0; p < 4; p++) {
                ldsm_x4(bt4, bsb + b_rb[p] + kx);
                bf[2 * p][0]     = bt4[0];
                bf[2 * p + 1][0] = bt4[1];
                bf[2 * p][1]     = bt4[2];
                bf[2 * p + 1][1] = bt4[3];
            }
#pragma unroll
            for (int mt = 0; mt < 2; mt++)
#pragma unroll
                for (int nt = 0; nt < 8; nt++)
                    mma_tf32(acc[mt][nt], af[mt], bf[nt]);
        }
    }

    // epilogue
#pragma unroll
    for (int mt = 0; mt < 2; mt++) {
        int r0 = m0 + wm * 32 + mt * 16 + g;
#pragma unroll
        for (int nt = 0; nt < 8; nt++) {
            int c = n0 + wn * 64 + nt * 8 + 2 * t;
            float2 b2 = *(const float2*)(bias + c);
            float2 v0 = make_float2(acc[mt][nt][0] + b2.x, acc[mt][nt][1] + b2.y);
            float2 v1 = make_float2(acc[mt][nt][2] + b2.x, acc[mt][nt][3] + b2.y);
            if (mode == 1) {
                v0.x = rn_tf32(v0.x); v0.y = rn_tf32(v0.y);
                v1.x = rn_tf32(v1.x); v1.y = rn_tf32(v1.y);
                if (c < 2048) {
                    int c0p = (c & ~7) | perm8(c & 7);
                    int c1p = (c & ~7) | perm8((c & 7) + 1);
                    C[(size_t)r0 * N + c0p] = v0.x;
                    C[(size_t)r0 * N + c1p] = v0.y;
                    C[(size_t)(r0 + 8) * N + c0p] = v1.x;
                    C[(size_t)(r0 + 8) * N + c1p] = v1.y;
                } else {
                    // V -> vt [b,h,d,token]; token dim uses pos_v permutation
                    int h  = (c - 2048) >> 6;
                    int d0 = (c - 2048) & 63;
                    int b0  = r0 >> 11;
                    int tp0 = ((r0 & 2047) & ~7) | posv(r0 & 7);
                    int tp1 = (((r0 + 8) & 2047) & ~7) | posv((r0 + 8) & 7);
                    float* vb = vt + ((size_t)(b0 * NH + h) * HD + d0) * TT;
                    vb[tp0]      = v0.x;
                    vb[TT + tp0] = v0.y;
                    vb[tp1]      = v1.x;
                    vb[TT + tp1] = v1.y;
                }
            } else {
                *(float2*)(C + (size_t)r0 * N + c) = v0;
                *(float2*)(C + (size_t)(r0 + 8) * N + c) = v1;
            }
        }
    }
}

// ---------------------------------------------------------------- attention
// Q [m][k-perm], K [n][k-perm], V [d][token pos_v]. P stays in registers:
// accumulator layout == A-fragment layout under reorder [c0,c2,c1,c3] when
// V tokens are pos_v-permuted. No P smem round-trip.
#define AQ 64
#define AK 64
#define SM_QS 0
#define SM_KS 4096
#define SM_VS (SM_KS + 2*4096)
#define ATTN_SMEM ((SM_VS + 2*4096) * 4)     // 81920 B

__global__ __launch_bounds__(128, 2) void attn_tc(const float* __restrict__ qkv,
                                                  const float* __restrict__ vt,
                                                  float* __restrict__ y)
{
    extern __shared__ float sm[];
    const int tid = threadIdx.x;
    const int wid = tid >> 5, lane = tid & 31;
    const int g = lane >> 2, t = lane & 3;
    const int qt = gridDim.x - 1 - blockIdx.x;
    const int h  = blockIdx.y;
    const int b  = blockIdx.z;
    const int q0 = qt * AQ;
    const int r0 = wid * 16 + g;
    const uint32_t smb = smem_u32(sm);

    // ldmatrix lane geometry
    const int lq = lane >> 3, li = lane & 7;
    const uint32_t sw4 = 4u * (uint32_t)li;
    const uint32_t ko  = (uint32_t)((lq >> 1) * 4);
    const uint32_t rq  = (uint32_t)((lq & 1) * 8 + li);
    const uint32_t q_rb = (uint32_t)(wid * 16 + rq) * 256u;
    uint32_t n_rb[4];
#pragma unroll
    for (int p = 0; p < 4; p++) n_rb[p] = (uint32_t)(p * 16 + rq) * 256u;

    // hoisted staging geometry
    uint32_t st_off[8], kg[8], vg[8];
#pragma unroll
    for (int i = 0; i < 8; i++) {
        int idx = tid + i * 128, row = idx >> 4, c4 = idx & 15;
        st_off[i] = (uint32_t)(row * 64 + ((c4 * 4) ^ (4 * (row & 7)))) * 4u;
        kg[i] = (uint32_t)(row * C3 + c4 * 4);
        vg[i] = (uint32_t)(row * TT + c4 * 4);
    }
    const float* kb0 = qkv + ((size_t)(b * TT)) * C3 + CC + h * HD;
    const float* vb0 = vt + ((size_t)(b * NH + h) * HD) * TT;

    // stage Q (scaled, swizzled)
    {
        const float* qbase = qkv + ((size_t)(b * TT + q0)) * C3 + h * HD;
#pragma unroll
        for (int i = 0; i < 8; i++) {
            int idx = tid + i * 128, row = idx >> 4, c4 = idx & 15;
            float4 v = *(const float4*)(qbase + (size_t)row * C3 + c4 * 4);
            v.x *= SCALE; v.y *= SCALE; v.z *= SCALE; v.w *= SCALE;
            *(float4*)(&sm[SM_QS + row * 64 + ((c4 * 4) ^ (4 * (row & 7)))]) = v;
        }
    }
    // prologue K/V tile 0
    {
        uint32_t kd = smb + SM_KS * 4, vd = smb + SM_VS * 4;
#pragma unroll
        for (int i = 0; i < 8; i++) {
            CP_ASYNC16(kd + st_off[i], kb0 + kg[i]);
            CP_ASYNC16(vd + st_off[i], vb0 + vg[i]);
        }
    }
    CP_COMMIT();
    __syncthreads();

    // Q fragments once
    uint32_t qf[8][4];
#pragma unroll
    for (int ds = 0; ds < 8; ds++)
        ldsm_x4(qf[ds], smb + SM_QS * 4 + q_rb + ((((uint32_t)(ds * 8) + ko) ^ sw4) << 2));

    float oacc[8][4];
#pragma unroll
    for (int nt = 0; nt < 8; nt++)
#pragma unroll
        for (int k = 0; k < 4; k++) oacc[nt][k] = 0.f;
    float mrow0 = -INFINITY, mrow1 = -INFINITY, lrow0 = 0.f, lrow1 = 0.f;

    const int pp0 = perm8(2 * t), pp1 = perm8(2 * t + 1);

    for (int kt = 0; kt <= qt; kt++) {
        const int buf = kt & 1;
        CP_WAIT(0);
        __syncthreads();
        if (kt < qt) {
            uint32_t kd = smb + (SM_KS + (buf ^ 1) * 4096) * 4;
            uint32_t vd = smb + (SM_VS + (buf ^ 1) * 4096) * 4;
            const float* kp = kb0 + (size_t)(kt + 1) * 64 * C3;
            const float* vp = vb0 + (kt + 1) * 64;
#pragma unroll
            for (int i = 0; i < 8; i++) {
                CP_ASYNC16(kd + st_off[i], kp + kg[i]);
                CP_ASYNC16(vd + st_off[i], vp + vg[i]);
            }
        }
        CP_COMMIT();

        const uint32_t ksb = smb + (SM_KS + buf * 4096) * 4;
        const uint32_t vsb = smb + (SM_VS + buf * 4096) * 4;

        // S = Q K^T
        float sacc[8][4];
#pragma unroll
        for (int nt = 0; nt < 8; nt++)
#pragma unroll
            for (int k = 0; k < 4; k++) sacc[nt][k] = 0.f;
#pragma unroll
        for (int ds = 0; ds < 8; ds++) {
            const uint32_t kx = (((uint32_t)(ds * 8) + ko) ^ sw4) << 2;
            uint32_t bf[8][2], bt4[4];
#pragma unroll
            for (int p = 0; p < 4; p++) {
                ldsm_x4(bt4, ksb + n_rb[p] + kx);
                bf[2 * p][0]     = bt4[0];
                bf[2 * p + 1][0] = bt4[1];
                bf[2 * p][1]     = bt4[2];
                bf[2 * p + 1][1] = bt4[3];
            }
#pragma unroll
            for (int nt = 0; nt < 8; nt++)
                mma_tf32(sacc[nt], qf[ds], bf[nt]);
        }

        if (kt == qt) {
#pragma unroll
            for (int nt = 0; nt < 8; nt++) {
                int c = nt * 8 + 2 * t;
                if (c     > r0)     sacc[nt][0] = -1e30f;
                if (c + 1 > r0)     sacc[nt][1] = -1e30f;
                if (c     > r0 + 8) sacc[nt][2] = -1e30f;
                if (c + 1 > r0 + 8) sacc[nt][3] = -1e30f;
            }
        }

        // online softmax
        float tm0 = -INFINITY, tm1 = -INFINITY;
#pragma unroll
        for (int nt = 0; nt < 8; nt++) {
            tm0 = fmaxf(tm0, fmaxf(sacc[nt][0], sacc[nt][1]));
            tm1 = fmaxf(tm1, fmaxf(sacc[nt][2], sacc[nt][3]));
        }
        tm0 = fmaxf(tm0, __shfl_xor_sync(0xffffffffu, tm0, 1));
        tm0 = fmaxf(tm0, __shfl_xor_sync(0xffffffffu, tm0, 2));
        tm1 = fmaxf(tm1, __shfl_xor_sync(0xffffffffu, tm1, 1));
        tm1 = fmaxf(tm1, __shfl_xor_sync(0xffffffffu, tm1, 2));
        float m0 = fmaxf(mrow0, tm0), m1 = fmaxf(mrow1, tm1);
        float a0 = __expf(mrow0 - m0), a1 = __expf(mrow1 - m1);
        mrow0 = m0; mrow1 = m1;
        float rs0 = 0.f, rs1 = 0.f;
#pragma unroll
        for (int nt = 0; nt < 8; nt++) {
            sacc[nt][0] = __expf(sacc[nt][0] - m0); rs0 += sacc[nt][0];
            sacc[nt][1] = __expf(sacc[nt][1] - m0); rs0 += sacc[nt][1];
            sacc[nt][2] = __expf(sacc[nt][2] - m1); rs1 += sacc[nt][2];
            sacc[nt][3] = __expf(sacc[nt][3] - m1); rs1 += sacc[nt][3];
        }
        rs0 += __shfl_xor_sync(0xffffffffu, rs0, 1);
        rs0 += __shfl_xor_sync(0xffffffffu, rs0, 2);
        rs1 += __shfl_xor_sync(0xffffffffu, rs1, 1);
        rs1 += __shfl_xor_sync(0xffffffffu, rs1, 2);
        lrow0 = lrow0 * a0 + rs0;
        lrow1 = lrow1 * a1 + rs1;
#pragma unroll
        for (int nt = 0; nt < 8; nt++) {
            oacc[nt][0] *= a0; oacc[nt][1] *= a0;
            oacc[nt][2] *= a1; oacc[nt][3] *= a1;
        }

        // O += P @ V — P directly from sacc registers (accumulator == A frag
        // under [c0,c2,c1,c3] with pos_v-permuted V tokens)
#pragma unroll
        for (int kk = 0; kk < 8; kk++) {
            const uint32_t kx = (((uint32_t)(kk * 8) + ko) ^ sw4) << 2;
            uint32_t af[4], bf[8][2], bt4[4];
            af[0] = __float_as_uint(rn_tf32(sacc[kk][0]));
            af[1] = __float_as_uint(rn_tf32(sacc[kk][2]));
            af[2] = __float_as_uint(rn_tf32(sacc[kk][1]));
            af[3] = __float_as_uint(rn_tf32(sacc[kk][3]));
#pragma unroll
            for (int p = 0; p < 4; p++) {
                ldsm_x4(bt4, vsb + n_rb[p] + kx);
                bf[2 * p][0]     = bt4[0];
                bf[2 * p + 1][0] = bt4[1];
                bf[2 * p][1]     = bt4[2];
                bf[2 * p + 1][1] = bt4[3];
            }
#pragma unroll
            for (int nt = 0; nt < 8; nt++)
                mma_tf32(oacc[nt], af, bf[nt]);
        }
    }

    // normalize + store, col-permuted (feeds proj GEMM's permuted A)
    float inv0 = 1.0f / lrow0, inv1 = 1.0f / lrow1;
    float* ybase = y + ((size_t)(b * TT + q0)) * CC + h * HD;
#pragma unroll
    for (int nt = 0; nt < 8; nt++) {
        int cb = nt * 8;
        ybase[(size_t)r0 * CC + cb + pp0]       = rn_tf32(oacc[nt][0] * inv0);
        ybase[(size_t)r0 * CC + cb + pp1]       = rn_tf32(oacc[nt][1] * inv0);
        ybase[(size_t)(r0 + 8) * CC + cb + pp0] = rn_tf32(oacc[nt][2] * inv1);
        ybase[(size_t)(r0 + 8) * CC + cb + pp1] = rn_tf32(oacc[nt][3] * inv1);
    }
}

// ---------------------------------------------------------------- launch
extern "C" void kernel_launch(void* const* d_in, const int* in_sizes, int n_in,
                              void* d_out, int out_size)
{
    const float* x      = (const float*)d_in[0];
    const float* w_attn = (const float*)d_in[1];
    const float* b_attn = (const float*)d_in[2];
    const float* w_proj = (const float*)d_in[3];
    const float* b_proj = (const float*)d_in[4];
    float* out = (float*)d_out;

    float *qkv, *vt, *yb, *xp, *waT, *wpT;
    cudaGetSymbolAddress((void**)&qkv, g_qkv);
    cudaGetSymbolAddress((void**)&vt,  g_vt);
    cudaGetSymbolAddress((void**)&yb,  g_y);
    cudaGetSymbolAddress((void**)&xp,  g_xp);
    cudaGetSymbolAddress((void**)&waT, g_waT);
    cudaGetSymbolAddress((void**)&wpT, g_wpT);

    cudaFuncSetAttribute(gemm_tf32, cudaFuncAttributeMaxDynamicSharedMemorySize, GEMM_SMEM);
    cudaFuncSetAttribute(attn_tc,   cudaFuncAttributeMaxDynamicSharedMemorySize, ATTN_SMEM);

    round_perm_kernel<<<(BT * CC) / (256 * 8), 256>>>(x, xp);
    transpose_perm_kernel<<<dim3(C3 / 32, CC / 32), dim3(32, 8)>>>(w_attn, waT, CC, C3);
    transpose_perm_kernel<<<dim3(CC / 32, CC / 32), dim3(32, 8)>>>(w_proj, wpT, CC, CC);

    gemm_tf32<<<dim3(C3 / GBN, BT / GBM), 256, GEMM_SMEM>>>(xp, waT, b_attn, qkv, vt,
                                                            BT, C3, CC, 1);

    attn_tc<<<dim3(TT / AQ, NH, BB), 128, ATTN_SMEM>>>(qkv, vt, yb);

    gemm_tf32<<<dim3(CC / GBN, BT / GBM), 256, GEMM_SMEM>>>(yb, wpT, b_proj, out, vt,
                                                            BT, CC, CC, 0);
}